// round 2
// baseline (speedup 1.0000x reference)
#include <cuda_runtime.h>
#include <cstdint>

#define B 8
#define L 512
#define H 20
#define D 1280
#define K 32

// Scratch (no allocations allowed in kernel_launch)
__device__ int   g_idx[2][B][K];  // top-K token indices per (rep, batch)
__device__ float g_u[4][D];       // u1, u2 (cls), v1, v2 (env)

// ---------------------------------------------------------------------------
// Kernel 1: per (rep, batch) block — head-mean of attn[b,:,pos[b],:],
// bitonic top-K=32 selection. Writes indices only (gather is deferred to K3).
// ---------------------------------------------------------------------------
__global__ void __launch_bounds__(512) k_topk(
    const float* __restrict__ attn1, const float* __restrict__ attn2,
    const int* __restrict__ pos)
{
    const int b = blockIdx.x;
    const int r = blockIdx.y;
    const float* attn = r ? attn2 : attn1;
    const int l = threadIdx.x;               // 0..511, one token per thread
    const int p = pos[b];

    // w[l] = mean over H heads of attn[b,h,p,l]
    const float* base = attn + ((size_t)b * H) * (size_t)(L * L)
                             + (size_t)p * L + l;
    float s = 0.f;
#pragma unroll
    for (int h = 0; h < H; ++h)
        s += base[(size_t)h * (L * L)];
    const float w = s * (1.0f / H);

    // Order-preserving uint key; tie-break toward smaller index (like jax top_k)
    __shared__ unsigned long long key[L];
    unsigned fb = __float_as_uint(w);
    fb = (fb & 0x80000000u) ? ~fb : (fb | 0x80000000u);
    key[l] = ((unsigned long long)fb << 32) | (unsigned)(L - 1 - l);
    __syncthreads();

    // Bitonic sort, descending. 512 elements, 45 compare/sync stages.
    for (int kk = 2; kk <= L; kk <<= 1) {
        for (int j = kk >> 1; j > 0; j >>= 1) {
            int ixj = l ^ j;
            if (ixj > l) {
                bool up = ((l & kk) == 0);
                unsigned long long a = key[l], c = key[ixj];
                if (up ? (a < c) : (a > c)) { key[l] = c; key[ixj] = a; }
            }
            __syncthreads();
        }
    }

    if (l < K)
        g_idx[r][b][l] = L - 1 - (int)(key[l] & 0xffffffffu);
}

// ---------------------------------------------------------------------------
// Kernel 2: dual matvec. For each matrix (cls_W / env_W), each row i:
//   u1[i] = sum_j W[i,j] * (c1[j]*wclf[j]);  u2[i] same with c2.
// One warp per row; W read exactly once. DRAM-bound (13 MB total).
// ---------------------------------------------------------------------------
__global__ void __launch_bounds__(256) k_matvec(
    const float* __restrict__ cls_W, const float* __restrict__ env_W,
    const float* __restrict__ clsclf_W, const float* __restrict__ envclf_W,
    const float* __restrict__ cls_c1, const float* __restrict__ cls_c2,
    const float* __restrict__ env_c1, const float* __restrict__ env_c2)
{
    const int mat = blockIdx.y;   // 0 = cls, 1 = env
    const float* W  = mat ? env_W    : cls_W;
    const float* wc = mat ? envclf_W : clsclf_W;
    const float* c1 = mat ? env_c1   : cls_c1;
    const float* c2 = mat ? env_c2   : cls_c2;

    const int warp = threadIdx.x >> 5;
    const int lane = threadIdx.x & 31;
    const int row  = blockIdx.x * 8 + warp;
    const float* Wr = W + (size_t)row * D;

    float a1 = 0.f, a2 = 0.f;
    // D=1280: 10 float4 iterations per lane
    for (int j = lane * 4; j < D; j += 128) {
        float4 wv  = *(const float4*)(Wr + j);
        float4 wcv = *(const float4*)(wc + j);
        float4 c1v = *(const float4*)(c1 + j);
        float4 c2v = *(const float4*)(c2 + j);
        float sx = wv.x * wcv.x, sy = wv.y * wcv.y,
              sz = wv.z * wcv.z, sw = wv.w * wcv.w;
        a1 += sx * c1v.x + sy * c1v.y + sz * c1v.z + sw * c1v.w;
        a2 += sx * c2v.x + sy * c2v.y + sz * c2v.z + sw * c2v.w;
    }
#pragma unroll
    for (int o = 16; o; o >>= 1) {
        a1 += __shfl_xor_sync(0xffffffffu, a1, o);
        a2 += __shfl_xor_sync(0xffffffffu, a2, o);
    }
    if (lane == 0) {
        g_u[mat * 2 + 0][row] = a1;
        g_u[mat * 2 + 1][row] = a2;
    }
}

// ---------------------------------------------------------------------------
// Kernel 3: one block per batch, 1024 threads (32 warps).
// 67 "tasks" per batch, distributed round-robin over warps:
//   task 0:      rep1[b,0] · u1
//   task 1:      rep2[b,0] · u2
//   tasks 2-33:  (1/K) * rep1[b, idx1[t]] · v1
//   tasks 34-65: (1/K) * rep2[b, idx2[t]] · v2
//   task 66:     bias constants dot
// Block reduce -> out[b] = (sum + clsclf_b + envclf_b) / 2
// ---------------------------------------------------------------------------
__global__ void __launch_bounds__(1024) k_final(
    const float* __restrict__ rep1, const float* __restrict__ rep2,
    const float* __restrict__ cls_b, const float* __restrict__ env_b,
    const float* __restrict__ clsclf_W, const float* __restrict__ envclf_W,
    const float* __restrict__ clsclf_b, const float* __restrict__ envclf_b,
    const float* __restrict__ cls_c1, const float* __restrict__ cls_c2,
    const float* __restrict__ env_c1, const float* __restrict__ env_c2,
    float* __restrict__ out)
{
    const int b    = blockIdx.x;
    const int warp = threadIdx.x >> 5;
    const int lane = threadIdx.x & 31;

    float wsum = 0.f;

    for (int task = warp; task < 67; task += 32) {
        if (task == 66) {
            // bias-constant dot (done by exactly one warp)
            float a = 0.f;
            for (int d = lane; d < D; d += 32)
                a += cls_b[d] * (cls_c1[d] + cls_c2[d]) * clsclf_W[d]
                   + env_b[d] * (env_c1[d] + env_c2[d]) * envclf_W[d];
            wsum += a;
            continue;
        }

        const float* row;
        const float* v;
        float scale;
        if (task == 0)      { row = rep1 + (size_t)b * L * D; v = g_u[0]; scale = 1.f; }
        else if (task == 1) { row = rep2 + (size_t)b * L * D; v = g_u[1]; scale = 1.f; }
        else if (task < 34) {
            int t = task - 2;
            row = rep1 + ((size_t)b * L + g_idx[0][b][t]) * D;
            v = g_u[2]; scale = 1.0f / K;
        } else {
            int t = task - 34;
            row = rep2 + ((size_t)b * L + g_idx[1][b][t]) * D;
            v = g_u[3]; scale = 1.0f / K;
        }

        float a = 0.f;
#pragma unroll
        for (int i = lane * 4; i < D; i += 128) {
            float4 rv = *(const float4*)(row + i);
            float4 vv = *(const float4*)(v + i);
            a += rv.x * vv.x + rv.y * vv.y + rv.z * vv.z + rv.w * vv.w;
        }
        wsum += a * scale;
    }

    // warp reduce
#pragma unroll
    for (int o = 16; o; o >>= 1)
        wsum += __shfl_xor_sync(0xffffffffu, wsum, o);

    __shared__ float red[32];
    if (lane == 0) red[warp] = wsum;
    __syncthreads();

    if (threadIdx.x < 32) {
        float t = red[threadIdx.x];
#pragma unroll
        for (int o = 16; o; o >>= 1)
            t += __shfl_xor_sync(0xffffffffu, t, o);
        if (threadIdx.x == 0)
            out[b] = (t + clsclf_b[0] + envclf_b[0]) * 0.5f;
    }
}

// ---------------------------------------------------------------------------
extern "C" void kernel_launch(void* const* d_in, const int* in_sizes, int n_in,
                              void* d_out, int out_size)
{
    const float* rep1     = (const float*)d_in[0];
    const float* rep2     = (const float*)d_in[1];
    const float* attn1    = (const float*)d_in[2];
    const float* attn2    = (const float*)d_in[3];
    const int*   pos      = (const int*)  d_in[4];
    const float* cls_W    = (const float*)d_in[5];
    const float* cls_b    = (const float*)d_in[6];
    const float* env_W    = (const float*)d_in[7];
    const float* env_b    = (const float*)d_in[8];
    const float* clsclf_W = (const float*)d_in[9];
    const float* clsclf_b = (const float*)d_in[10];
    const float* envclf_W = (const float*)d_in[11];
    const float* envclf_b = (const float*)d_in[12];
    const float* cls_c1   = (const float*)d_in[13];
    const float* cls_c2   = (const float*)d_in[14];
    const float* env_c1   = (const float*)d_in[15];
    const float* env_c2   = (const float*)d_in[16];
    float* out = (float*)d_out;

    dim3 g1(B, 2);
    k_topk<<<g1, 512>>>(attn1, attn2, pos);

    dim3 g2(D / 8, 2);
    k_matvec<<<g2, 256>>>(cls_W, env_W, clsclf_W, envclf_W,
                          cls_c1, cls_c2, env_c1, env_c2);

    k_final<<<B, 1024>>>(rep1, rep2, cls_b, env_b,
                         clsclf_W, envclf_W, clsclf_b, envclf_b,
                         cls_c1, cls_c2, env_c1, env_c2, out);
}

// round 3
// speedup vs baseline: 1.2670x; 1.2670x over previous
#include <cuda_runtime.h>
#include <cstdint>

#define B 8
#define L 512
#define H 20
#define D 1280
#define K 32

#define MATVEC_BLOCKS 160   // 16 warps/block * 160 = 2560 rows = 2 matrices * D
#define TOPK_BLOCKS   16    // 2 reps * 8 batches

// Scratch (no allocations allowed in kernel_launch)
__device__ int   g_idx[2][B][K];   // top-K token indices per (rep, batch)
__device__ float g_u[4][D];        // u1, u2 (cls), v1, v2 (env)
__device__ float g_part[66][B];    // per-task partial dots
__device__ float g_bias;           // batch-independent bias dot

// ---------------------------------------------------------------------------
// Warp-register bitonic sort, 32 u64 keys across lanes, DESCENDING.
// (ascending network applied to ~key)
// ---------------------------------------------------------------------------
__device__ __forceinline__ unsigned long long warp_sort_desc(
    unsigned long long key, int lane)
{
    unsigned long long v = ~key;
#pragma unroll
    for (int k = 2; k <= 32; k <<= 1) {
#pragma unroll
        for (int j = k >> 1; j > 0; j >>= 1) {
            unsigned long long other = __shfl_xor_sync(0xffffffffu, v, j);
            bool lower = (lane & j) == 0;
            bool up    = (lane & k) == 0;
            unsigned long long mn = (v < other) ? v : other;
            unsigned long long mx = (v < other) ? other : v;
            v = (lower == up) ? mn : mx;
        }
    }
    return ~v;   // lane i now holds i-th LARGEST original key
}

// ---------------------------------------------------------------------------
// Kernel 1 (fused): blocks [0,160) do the dual matvec; blocks [160,176) do
// head-mean + top-K for one (rep, batch).
// ---------------------------------------------------------------------------
__global__ void __launch_bounds__(512) k_fused(
    const float* __restrict__ attn1, const float* __restrict__ attn2,
    const int* __restrict__ pos,
    const float* __restrict__ cls_W, const float* __restrict__ env_W,
    const float* __restrict__ clsclf_W, const float* __restrict__ envclf_W,
    const float* __restrict__ cls_c1, const float* __restrict__ cls_c2,
    const float* __restrict__ env_c1, const float* __restrict__ env_c2)
{
    const int warp = threadIdx.x >> 5;
    const int lane = threadIdx.x & 31;

    if (blockIdx.x < MATVEC_BLOCKS) {
        // ---------- dual matvec: one warp per W row, W read exactly once ----
        const int grow = blockIdx.x * 16 + warp;        // 0..2559
        const int mat  = grow >= D;                     // 0 = cls, 1 = env
        const int row  = grow - mat * D;
        const float* W  = mat ? env_W    : cls_W;
        const float* wc = mat ? envclf_W : clsclf_W;
        const float* c1 = mat ? env_c1   : cls_c1;
        const float* c2 = mat ? env_c2   : cls_c2;
        const float* Wr = W + (size_t)row * D;

        float a1 = 0.f, a2 = 0.f;
#pragma unroll
        for (int j = lane * 4; j < D; j += 128) {
            float4 wv  = *(const float4*)(Wr + j);
            float4 wcv = *(const float4*)(wc + j);
            float4 c1v = *(const float4*)(c1 + j);
            float4 c2v = *(const float4*)(c2 + j);
            float sx = wv.x * wcv.x, sy = wv.y * wcv.y,
                  sz = wv.z * wcv.z, sw = wv.w * wcv.w;
            a1 += sx * c1v.x + sy * c1v.y + sz * c1v.z + sw * c1v.w;
            a2 += sx * c2v.x + sy * c2v.y + sz * c2v.z + sw * c2v.w;
        }
#pragma unroll
        for (int o = 16; o; o >>= 1) {
            a1 += __shfl_xor_sync(0xffffffffu, a1, o);
            a2 += __shfl_xor_sync(0xffffffffu, a2, o);
        }
        if (lane == 0) {
            g_u[mat * 2 + 0][row] = a1;
            g_u[mat * 2 + 1][row] = a2;
        }
        return;
    }

    // ---------- top-K for one (rep, batch) -------------------------------
    const int tb = blockIdx.x - MATVEC_BLOCKS;   // 0..15
    const int b  = tb & 7;
    const int r  = tb >> 3;
    const float* attn = r ? attn2 : attn1;
    const int l = threadIdx.x;                   // token 0..511
    const int p = pos[b];

    // w[l] = mean over H heads of attn[b,h,p,l]
    const float* base = attn + ((size_t)b * H) * (size_t)(L * L)
                             + (size_t)p * L + l;
    float s = 0.f;
#pragma unroll
    for (int h = 0; h < H; ++h)
        s += base[(size_t)h * (L * L)];

    // Order-preserving key; low bits = L-1-l so larger packed key among
    // equal values means smaller token index (jax tie-break).
    unsigned fb = __float_as_uint(s * (1.0f / H));
    fb = (fb & 0x80000000u) ? ~fb : (fb | 0x80000000u);
    unsigned long long key =
        ((unsigned long long)fb << 32) | (unsigned)(L - 1 - l);

    // Per-warp register sort (descending), no barriers.
    key = warp_sort_desc(key, lane);

    __shared__ unsigned long long sorted[16][32];
    sorted[warp][lane] = key;
    __syncthreads();

    // Warp 0 merges the 16 sorted lists, extracting global top-K.
    if (warp == 0) {
        unsigned long long h = (lane < 16) ? sorted[lane][0] : 0ull;
        int ptr = 0;
#pragma unroll
        for (int i = 0; i < K; ++i) {
            unsigned long long m = h;
#pragma unroll
            for (int o = 8; o; o >>= 1) {       // lanes 16-31 hold 0
                unsigned long long other = __shfl_xor_sync(0xffffffffu, m, o);
                if (other > m) m = other;
            }
            m = __shfl_sync(0xffffffffu, m, 0); // broadcast max of lanes 0..15
            if (h == m) {                       // unique keys -> one winner
                g_idx[r][b][i] = L - 1 - (int)(m & 0xffffffffu);
                ++ptr;
                h = (ptr < 32) ? sorted[lane][ptr] : 0ull;
            }
        }
    }
}

// ---------------------------------------------------------------------------
// Kernel 2: 67 blocks, 256 threads. Block t computes task t for all 8
// batches (one warp per batch); block 66 computes the bias dot.
//   t==0:      rep1[b,0] . u1
//   t==1:      rep2[b,0] . u2
//   t in 2-33: (1/K) * rep1[b, idx1[t-2]]  . v1
//   t in 34-65:(1/K) * rep2[b, idx2[t-34]] . v2
// ---------------------------------------------------------------------------
__global__ void __launch_bounds__(256) k_dots(
    const float* __restrict__ rep1, const float* __restrict__ rep2,
    const float* __restrict__ cls_b, const float* __restrict__ env_b,
    const float* __restrict__ clsclf_W, const float* __restrict__ envclf_W,
    const float* __restrict__ cls_c1, const float* __restrict__ cls_c2,
    const float* __restrict__ env_c1, const float* __restrict__ env_c2)
{
    const int t    = blockIdx.x;
    const int warp = threadIdx.x >> 5;
    const int lane = threadIdx.x & 31;

    if (t == 66) {
        if (warp != 0) return;
        float a = 0.f;
        for (int d = lane; d < D; d += 32)
            a += cls_b[d] * (cls_c1[d] + cls_c2[d]) * clsclf_W[d]
               + env_b[d] * (env_c1[d] + env_c2[d]) * envclf_W[d];
#pragma unroll
        for (int o = 16; o; o >>= 1)
            a += __shfl_xor_sync(0xffffffffu, a, o);
        if (lane == 0) g_bias = a;
        return;
    }

    const int b = warp;   // 8 warps = 8 batches
    const float* row;
    const float* v;
    float scale;
    if (t == 0)      { row = rep1 + (size_t)b * L * D; v = g_u[0]; scale = 1.f; }
    else if (t == 1) { row = rep2 + (size_t)b * L * D; v = g_u[1]; scale = 1.f; }
    else if (t < 34) {
        row = rep1 + ((size_t)b * L + g_idx[0][b][t - 2]) * D;
        v = g_u[2]; scale = 1.0f / K;
    } else {
        row = rep2 + ((size_t)b * L + g_idx[1][b][t - 34]) * D;
        v = g_u[3]; scale = 1.0f / K;
    }

    float a = 0.f;
#pragma unroll
    for (int i = lane * 4; i < D; i += 128) {
        float4 rv = *(const float4*)(row + i);
        float4 vv = *(const float4*)(v + i);
        a += rv.x * vv.x + rv.y * vv.y + rv.z * vv.z + rv.w * vv.w;
    }
#pragma unroll
    for (int o = 16; o; o >>= 1)
        a += __shfl_xor_sync(0xffffffffu, a, o);
    if (lane == 0) g_part[t][b] = a * scale;
}

// ---------------------------------------------------------------------------
// Kernel 3: 1 block, 256 threads; warp b sums its 66 partials + biases.
// ---------------------------------------------------------------------------
__global__ void __launch_bounds__(256) k_final(
    const float* __restrict__ clsclf_b, const float* __restrict__ envclf_b,
    float* __restrict__ out)
{
    const int b    = threadIdx.x >> 5;
    const int lane = threadIdx.x & 31;

    float s = 0.f;
    for (int t = lane; t < 66; t += 32)
        s += g_part[t][b];
#pragma unroll
    for (int o = 16; o; o >>= 1)
        s += __shfl_xor_sync(0xffffffffu, s, o);
    if (lane == 0)
        out[b] = (s + g_bias + clsclf_b[0] + envclf_b[0]) * 0.5f;
}

// ---------------------------------------------------------------------------
extern "C" void kernel_launch(void* const* d_in, const int* in_sizes, int n_in,
                              void* d_out, int out_size)
{
    const float* rep1     = (const float*)d_in[0];
    const float* rep2     = (const float*)d_in[1];
    const float* attn1    = (const float*)d_in[2];
    const float* attn2    = (const float*)d_in[3];
    const int*   pos      = (const int*)  d_in[4];
    const float* cls_W    = (const float*)d_in[5];
    const float* cls_b    = (const float*)d_in[6];
    const float* env_W    = (const float*)d_in[7];
    const float* env_b    = (const float*)d_in[8];
    const float* clsclf_W = (const float*)d_in[9];
    const float* clsclf_b = (const float*)d_in[10];
    const float* envclf_W = (const float*)d_in[11];
    const float* envclf_b = (const float*)d_in[12];
    const float* cls_c1   = (const float*)d_in[13];
    const float* cls_c2   = (const float*)d_in[14];
    const float* env_c1   = (const float*)d_in[15];
    const float* env_c2   = (const float*)d_in[16];
    float* out = (float*)d_out;

    k_fused<<<MATVEC_BLOCKS + TOPK_BLOCKS, 512>>>(
        attn1, attn2, pos, cls_W, env_W, clsclf_W, envclf_W,
        cls_c1, cls_c2, env_c1, env_c2);

    k_dots<<<67, 256>>>(rep1, rep2, cls_b, env_b,
                        clsclf_W, envclf_W,
                        cls_c1, cls_c2, env_c1, env_c2);

    k_final<<<1, 256>>>(clsclf_b, envclf_b, out);
}

// round 4
// speedup vs baseline: 1.5415x; 1.2166x over previous
#include <cuda_runtime.h>
#include <cstdint>

#define B 8
#define L 512
#define H 20
#define D 1280
#define K 32

#define MATVEC_BLOCKS 320   // 16 warps * 320 = 5120 half-rows = 2*2560 rows
#define TOPK_BLOCKS   16    // 2 reps * 8 batches
#define BIAS_BLOCKS   1
#define DOT_BLOCKS    66

// Scratch (no allocations allowed in kernel_launch)
__device__ int   g_idx[2][B][K];    // top-K token indices per (rep, batch)
__device__ float g_up[2][4][D];     // half-row partials of u1,u2,v1,v2
__device__ float g_part[66][B];     // per-task partial dots
__device__ float g_bias;            // batch-independent bias dot
__device__ int   g_ctr;             // k_dots completion counter (self-resetting)

// ---------------------------------------------------------------------------
// Warp-register bitonic sort, 32 u64 keys across lanes, DESCENDING.
// ---------------------------------------------------------------------------
__device__ __forceinline__ unsigned long long warp_sort_desc(
    unsigned long long key, int lane)
{
    unsigned long long v = ~key;
#pragma unroll
    for (int k = 2; k <= 32; k <<= 1) {
#pragma unroll
        for (int j = k >> 1; j > 0; j >>= 1) {
            unsigned long long other = __shfl_xor_sync(0xffffffffu, v, j);
            bool lower = (lane & j) == 0;
            bool up    = (lane & k) == 0;
            unsigned long long mn = (v < other) ? v : other;
            unsigned long long mx = (v < other) ? other : v;
            v = (lower == up) ? mn : mx;
        }
    }
    return ~v;   // lane i holds i-th LARGEST original key
}

// ---------------------------------------------------------------------------
// Kernel 1 (fused): [0,320) dual matvec half-rows; [320,336) top-K; 336 bias.
// ---------------------------------------------------------------------------
__global__ void __launch_bounds__(512) k_fused(
    const float* __restrict__ attn1, const float* __restrict__ attn2,
    const int* __restrict__ pos,
    const float* __restrict__ cls_W, const float* __restrict__ env_W,
    const float* __restrict__ cls_b, const float* __restrict__ env_b,
    const float* __restrict__ clsclf_W, const float* __restrict__ envclf_W,
    const float* __restrict__ cls_c1, const float* __restrict__ cls_c2,
    const float* __restrict__ env_c1, const float* __restrict__ env_c2)
{
    const int warp = threadIdx.x >> 5;
    const int lane = threadIdx.x & 31;

    if (blockIdx.x < MATVEC_BLOCKS) {
        // --- dual matvec: one warp per HALF row (640 floats, 5 float4/lane)
        const int gw   = blockIdx.x * 16 + warp;   // 0..5119
        const int half = gw & 1;
        const int grow = gw >> 1;                  // 0..2559
        const int mat  = grow >= D;                // 0 = cls, 1 = env
        const int row  = grow - mat * D;
        const float* W  = mat ? env_W    : cls_W;
        const float* wc = mat ? envclf_W : clsclf_W;
        const float* c1 = mat ? env_c1   : cls_c1;
        const float* c2 = mat ? env_c2   : cls_c2;
        const float* Wr = W + (size_t)row * D;
        const int j0 = half * (D / 2) + lane * 4;

        float a1 = 0.f, a2 = 0.f;
#pragma unroll
        for (int it = 0; it < 5; ++it) {
            int j = j0 + it * 128;
            float4 wv  = *(const float4*)(Wr + j);
            float4 wcv = *(const float4*)(wc + j);
            float4 c1v = *(const float4*)(c1 + j);
            float4 c2v = *(const float4*)(c2 + j);
            float sx = wv.x * wcv.x, sy = wv.y * wcv.y,
                  sz = wv.z * wcv.z, sw = wv.w * wcv.w;
            a1 += sx * c1v.x + sy * c1v.y + sz * c1v.z + sw * c1v.w;
            a2 += sx * c2v.x + sy * c2v.y + sz * c2v.z + sw * c2v.w;
        }
#pragma unroll
        for (int o = 16; o; o >>= 1) {
            a1 += __shfl_xor_sync(0xffffffffu, a1, o);
            a2 += __shfl_xor_sync(0xffffffffu, a2, o);
        }
        if (lane == 0) {
            g_up[half][mat * 2 + 0][row] = a1;
            g_up[half][mat * 2 + 1][row] = a2;
        }
        return;
    }

    if (blockIdx.x == MATVEC_BLOCKS + TOPK_BLOCKS) {
        // --- bias dot (one warp) ---
        if (warp != 0) return;
        float a = 0.f;
        for (int d = lane; d < D; d += 32)
            a += cls_b[d] * (cls_c1[d] + cls_c2[d]) * clsclf_W[d]
               + env_b[d] * (env_c1[d] + env_c2[d]) * envclf_W[d];
#pragma unroll
        for (int o = 16; o; o >>= 1)
            a += __shfl_xor_sync(0xffffffffu, a, o);
        if (lane == 0) g_bias = a;
        return;
    }

    // --- top-K for one (rep, batch) ---
    const int tb = blockIdx.x - MATVEC_BLOCKS;   // 0..15
    const int b  = tb & 7;
    const int r  = tb >> 3;
    const float* attn = r ? attn2 : attn1;
    const int l = threadIdx.x;                   // token 0..511
    const int p = pos[b];

    const float* base = attn + ((size_t)b * H) * (size_t)(L * L)
                             + (size_t)p * L + l;
    float s = 0.f;
#pragma unroll
    for (int h = 0; h < H; ++h)
        s += base[(size_t)h * (L * L)];

    unsigned fb = __float_as_uint(s * (1.0f / H));
    fb = (fb & 0x80000000u) ? ~fb : (fb | 0x80000000u);
    unsigned long long key =
        ((unsigned long long)fb << 32) | (unsigned)(L - 1 - l);

    key = warp_sort_desc(key, lane);

    __shared__ unsigned long long sorted[16][32];
    sorted[warp][lane] = key;
    __syncthreads();

    if (warp == 0) {
        unsigned long long h = (lane < 16) ? sorted[lane][0] : 0ull;
        int ptr = 0;
#pragma unroll
        for (int i = 0; i < K; ++i) {
            unsigned long long m = h;
#pragma unroll
            for (int o = 8; o; o >>= 1) {
                unsigned long long other = __shfl_xor_sync(0xffffffffu, m, o);
                if (other > m) m = other;
            }
            m = __shfl_sync(0xffffffffu, m, 0);
            if (h == m) {
                g_idx[r][b][i] = L - 1 - (int)(m & 0xffffffffu);
                ++ptr;
                h = (ptr < 32) ? sorted[lane][ptr] : 0ull;
            }
        }
    }
}

// ---------------------------------------------------------------------------
// Kernel 2: 66 blocks, 256 threads. Block t computes task t for all 8
// batches (one warp per batch). Last block to finish also produces out[].
// ---------------------------------------------------------------------------
__global__ void __launch_bounds__(256) k_dots(
    const float* __restrict__ rep1, const float* __restrict__ rep2,
    const float* __restrict__ clsclf_b, const float* __restrict__ envclf_b,
    float* __restrict__ out)
{
    const int t    = blockIdx.x;
    const int warp = threadIdx.x >> 5;
    const int lane = threadIdx.x & 31;
    const int b    = warp;   // 8 warps = 8 batches

    const float* row;
    int vi;
    float scale;
    if (t == 0)      { row = rep1 + (size_t)b * L * D; vi = 0; scale = 1.f; }
    else if (t == 1) { row = rep2 + (size_t)b * L * D; vi = 1; scale = 1.f; }
    else if (t < 34) {
        row = rep1 + ((size_t)b * L + g_idx[0][b][t - 2]) * D;
        vi = 2; scale = 1.0f / K;
    } else {
        row = rep2 + ((size_t)b * L + g_idx[1][b][t - 34]) * D;
        vi = 3; scale = 1.0f / K;
    }
    const float* v0 = g_up[0][vi];
    const float* v1 = g_up[1][vi];

    float a = 0.f;
#pragma unroll
    for (int i = lane * 4; i < D; i += 128) {
        float4 rv  = *(const float4*)(row + i);
        float4 va  = *(const float4*)(v0 + i);
        float4 vb  = *(const float4*)(v1 + i);
        a += rv.x * (va.x + vb.x) + rv.y * (va.y + vb.y)
           + rv.z * (va.z + vb.z) + rv.w * (va.w + vb.w);
    }
#pragma unroll
    for (int o = 16; o; o >>= 1)
        a += __shfl_xor_sync(0xffffffffu, a, o);
    if (lane == 0) g_part[t][b] = a * scale;

    // ---- last-block-done final reduction (replaces a 3rd kernel) ----
    __syncthreads();
    __shared__ int is_last;
    if (threadIdx.x == 0) {
        __threadfence();
        is_last = (atomicAdd(&g_ctr, 1) == DOT_BLOCKS - 1);
    }
    __syncthreads();
    if (!is_last) return;

    __threadfence();   // acquire all g_part writes
    if (warp < 8) {    // warp b sums its 66 partials
        float s = 0.f;
        for (int tt = lane; tt < 66; tt += 32)
            s += g_part[tt][b];
#pragma unroll
        for (int o = 16; o; o >>= 1)
            s += __shfl_xor_sync(0xffffffffu, s, o);
        if (lane == 0)
            out[b] = (s + g_bias + clsclf_b[0] + envclf_b[0]) * 0.5f;
    }
    if (threadIdx.x == 0) g_ctr = 0;   // reset for next graph replay
}

// ---------------------------------------------------------------------------
extern "C" void kernel_launch(void* const* d_in, const int* in_sizes, int n_in,
                              void* d_out, int out_size)
{
    const float* rep1     = (const float*)d_in[0];
    const float* rep2     = (const float*)d_in[1];
    const float* attn1    = (const float*)d_in[2];
    const float* attn2    = (const float*)d_in[3];
    const int*   pos      = (const int*)  d_in[4];
    const float* cls_W    = (const float*)d_in[5];
    const float* cls_b    = (const float*)d_in[6];
    const float* env_W    = (const float*)d_in[7];
    const float* env_b    = (const float*)d_in[8];
    const float* clsclf_W = (const float*)d_in[9];
    const float* clsclf_b = (const float*)d_in[10];
    const float* envclf_W = (const float*)d_in[11];
    const float* envclf_b = (const float*)d_in[12];
    const float* cls_c1   = (const float*)d_in[13];
    const float* cls_c2   = (const float*)d_in[14];
    const float* env_c1   = (const float*)d_in[15];
    const float* env_c2   = (const float*)d_in[16];
    float* out = (float*)d_out;

    k_fused<<<MATVEC_BLOCKS + TOPK_BLOCKS + BIAS_BLOCKS, 512>>>(
        attn1, attn2, pos, cls_W, env_W, cls_b, env_b,
        clsclf_W, envclf_W, cls_c1, cls_c2, env_c1, env_c2);

    k_dots<<<DOT_BLOCKS, 256>>>(rep1, rep2, clsclf_b, envclf_b, out);
}

// round 5
// speedup vs baseline: 1.6996x; 1.1026x over previous
#include <cuda_runtime.h>
#include <cstdint>

#define B 8
#define L 512
#define H 20
#define D 1280
#define K 32

#define MATVEC_BLOCKS 320   // 16 warps * 320 = 5120 half-rows = 2*2560 rows
#define TOPK_BLOCKS   16    // 2 reps * 8 batches
#define BIAS_BLOCKS   1
#define DOT_BLOCKS    132   // 66 tasks * 2 D-halves

// Scratch (no allocations allowed in kernel_launch)
__device__ int   g_idx[2][B][K];    // top-K token indices per (rep, batch)
__device__ float g_up[2][4][D];     // j-half partials of u1,u2,v1,v2
__device__ float g_part[DOT_BLOCKS][B];
__device__ float g_bias;            // batch-independent bias dot
__device__ int   g_ctr;             // k_dots completion counter (self-resetting)

// ---------------------------------------------------------------------------
// Warp-register bitonic sort, 32 u64 keys across lanes, DESCENDING.
// ---------------------------------------------------------------------------
__device__ __forceinline__ unsigned long long warp_sort_desc(
    unsigned long long key, int lane)
{
    unsigned long long v = ~key;
#pragma unroll
    for (int k = 2; k <= 32; k <<= 1) {
#pragma unroll
        for (int j = k >> 1; j > 0; j >>= 1) {
            unsigned long long other = __shfl_xor_sync(0xffffffffu, v, j);
            bool lower = (lane & j) == 0;
            bool up    = (lane & k) == 0;
            unsigned long long mn = (v < other) ? v : other;
            unsigned long long mx = (v < other) ? other : v;
            v = (lower == up) ? mn : mx;
        }
    }
    return ~v;   // lane i holds i-th LARGEST original key
}

// ---------------------------------------------------------------------------
// Kernel 1 (fused): [0,320) dual matvec half-rows; [320,336) top-K; 336 bias.
// ---------------------------------------------------------------------------
__global__ void __launch_bounds__(512) k_fused(
    const float* __restrict__ attn1, const float* __restrict__ attn2,
    const int* __restrict__ pos,
    const float* __restrict__ cls_W, const float* __restrict__ env_W,
    const float* __restrict__ cls_b, const float* __restrict__ env_b,
    const float* __restrict__ clsclf_W, const float* __restrict__ envclf_W,
    const float* __restrict__ cls_c1, const float* __restrict__ cls_c2,
    const float* __restrict__ env_c1, const float* __restrict__ env_c2)
{
    const int warp = threadIdx.x >> 5;
    const int lane = threadIdx.x & 31;

    if (blockIdx.x < MATVEC_BLOCKS) {
        // --- dual matvec: one warp per HALF row (640 floats, 5 float4/lane)
        const int gw   = blockIdx.x * 16 + warp;   // 0..5119
        const int half = gw & 1;
        const int grow = gw >> 1;                  // 0..2559
        const int mat  = grow >= D;                // 0 = cls, 1 = env
        const int row  = grow - mat * D;
        const float* W  = mat ? env_W    : cls_W;
        const float* wc = mat ? envclf_W : clsclf_W;
        const float* c1 = mat ? env_c1   : cls_c1;
        const float* c2 = mat ? env_c2   : cls_c2;
        const float* Wr = W + (size_t)row * D;
        const int j0 = half * (D / 2) + lane * 4;

        // Front-batch the 5 DRAM loads of the W half-row (max MLP).
        float4 wv[5];
#pragma unroll
        for (int it = 0; it < 5; ++it)
            wv[it] = *(const float4*)(Wr + j0 + it * 128);

        float a1 = 0.f, a2 = 0.f;
#pragma unroll
        for (int it = 0; it < 5; ++it) {
            const int j = j0 + it * 128;
            float4 wcv = *(const float4*)(wc + j);   // L1/L2-hot (5 KB)
            float4 c1v = *(const float4*)(c1 + j);
            float4 c2v = *(const float4*)(c2 + j);
            float sx = wv[it].x * wcv.x, sy = wv[it].y * wcv.y,
                  sz = wv[it].z * wcv.z, sw = wv[it].w * wcv.w;
            a1 += sx * c1v.x + sy * c1v.y + sz * c1v.z + sw * c1v.w;
            a2 += sx * c2v.x + sy * c2v.y + sz * c2v.z + sw * c2v.w;
        }
#pragma unroll
        for (int o = 16; o; o >>= 1) {
            a1 += __shfl_xor_sync(0xffffffffu, a1, o);
            a2 += __shfl_xor_sync(0xffffffffu, a2, o);
        }
        if (lane == 0) {
            g_up[half][mat * 2 + 0][row] = a1;
            g_up[half][mat * 2 + 1][row] = a2;
        }
        return;
    }

    if (blockIdx.x == MATVEC_BLOCKS + TOPK_BLOCKS) {
        // --- bias dot (one warp) ---
        if (warp != 0) return;
        float a = 0.f;
        for (int d = lane; d < D; d += 32)
            a += cls_b[d] * (cls_c1[d] + cls_c2[d]) * clsclf_W[d]
               + env_b[d] * (env_c1[d] + env_c2[d]) * envclf_W[d];
#pragma unroll
        for (int o = 16; o; o >>= 1)
            a += __shfl_xor_sync(0xffffffffu, a, o);
        if (lane == 0) g_bias = a;
        return;
    }

    // --- top-K for one (rep, batch) ---
    const int tb = blockIdx.x - MATVEC_BLOCKS;   // 0..15
    const int b  = tb & 7;
    const int r  = tb >> 3;
    const float* attn = r ? attn2 : attn1;
    const int l = threadIdx.x;                   // token 0..511
    const int p = pos[b];

    const float* base = attn + ((size_t)b * H) * (size_t)(L * L)
                             + (size_t)p * L + l;
    float s = 0.f;
#pragma unroll
    for (int h = 0; h < H; ++h)
        s += base[(size_t)h * (L * L)];

    unsigned fb = __float_as_uint(s * (1.0f / H));
    fb = (fb & 0x80000000u) ? ~fb : (fb | 0x80000000u);
    unsigned long long key =
        ((unsigned long long)fb << 32) | (unsigned)(L - 1 - l);

    key = warp_sort_desc(key, lane);

    __shared__ unsigned long long sorted[16][32];
    sorted[warp][lane] = key;
    __syncthreads();

    if (warp == 0) {
        unsigned long long h = (lane < 16) ? sorted[lane][0] : 0ull;
        int ptr = 0;
#pragma unroll
        for (int i = 0; i < K; ++i) {
            unsigned long long m = h;
#pragma unroll
            for (int o = 8; o; o >>= 1) {
                unsigned long long other = __shfl_xor_sync(0xffffffffu, m, o);
                if (other > m) m = other;
            }
            m = __shfl_sync(0xffffffffu, m, 0);
            if (h == m) {
                g_idx[r][b][i] = L - 1 - (int)(m & 0xffffffffu);
                ++ptr;
                h = (ptr < 32) ? sorted[lane][ptr] : 0ull;
            }
        }
    }
}

// ---------------------------------------------------------------------------
// Kernel 2: 132 blocks (task t, D-half hh), 256 threads (warp = batch).
// Each warp dots 640 floats of one rep row against the rebuilt v slice.
// Last finished block sums all partials and writes out[].
// ---------------------------------------------------------------------------
__global__ void __launch_bounds__(256) k_dots(
    const float* __restrict__ rep1, const float* __restrict__ rep2,
    const float* __restrict__ clsclf_b, const float* __restrict__ envclf_b,
    float* __restrict__ out)
{
    const int t    = blockIdx.x >> 1;    // task 0..65
    const int hh   = blockIdx.x & 1;     // D-half
    const int warp = threadIdx.x >> 5;
    const int lane = threadIdx.x & 31;
    const int b    = warp;               // 8 warps = 8 batches

    const float* row;
    int vi;
    float scale;
    if (t == 0)      { row = rep1 + (size_t)b * L * D; vi = 0; scale = 1.f; }
    else if (t == 1) { row = rep2 + (size_t)b * L * D; vi = 1; scale = 1.f; }
    else if (t < 34) {
        row = rep1 + ((size_t)b * L + g_idx[0][b][t - 2]) * D;
        vi = 2; scale = 1.0f / K;
    } else {
        row = rep2 + ((size_t)b * L + g_idx[1][b][t - 34]) * D;
        vi = 3; scale = 1.0f / K;
    }
    const float* v0 = g_up[0][vi];
    const float* v1 = g_up[1][vi];
    const int i0 = hh * (D / 2) + lane * 4;

    // Front-batch the 5 DRAM loads of the rep-row half (max MLP).
    float4 rv[5];
#pragma unroll
    for (int it = 0; it < 5; ++it)
        rv[it] = *(const float4*)(row + i0 + it * 128);

    float a = 0.f;
#pragma unroll
    for (int it = 0; it < 5; ++it) {
        const int i = i0 + it * 128;
        float4 va = *(const float4*)(v0 + i);    // L2-hot (20 KB total)
        float4 vb = *(const float4*)(v1 + i);
        a += rv[it].x * (va.x + vb.x) + rv[it].y * (va.y + vb.y)
           + rv[it].z * (va.z + vb.z) + rv[it].w * (va.w + vb.w);
    }
#pragma unroll
    for (int o = 16; o; o >>= 1)
        a += __shfl_xor_sync(0xffffffffu, a, o);
    if (lane == 0) g_part[blockIdx.x][b] = a * scale;

    // ---- last-block-done final reduction ----
    __syncthreads();
    __shared__ int is_last;
    if (threadIdx.x == 0) {
        __threadfence();
        is_last = (atomicAdd(&g_ctr, 1) == DOT_BLOCKS - 1);
    }
    __syncthreads();
    if (!is_last) return;

    __threadfence();   // acquire all g_part writes
    if (warp < 8) {    // warp b sums its 132 partials
        float s = 0.f;
        for (int tt = lane; tt < DOT_BLOCKS; tt += 32)
            s += g_part[tt][b];
#pragma unroll
        for (int o = 16; o; o >>= 1)
            s += __shfl_xor_sync(0xffffffffu, s, o);
        if (lane == 0)
            out[b] = (s + g_bias + clsclf_b[0] + envclf_b[0]) * 0.5f;
    }
    if (threadIdx.x == 0) g_ctr = 0;   // reset for next graph replay
}

// ---------------------------------------------------------------------------
extern "C" void kernel_launch(void* const* d_in, const int* in_sizes, int n_in,
                              void* d_out, int out_size)
{
    const float* rep1     = (const float*)d_in[0];
    const float* rep2     = (const float*)d_in[1];
    const float* attn1    = (const float*)d_in[2];
    const float* attn2    = (const float*)d_in[3];
    const int*   pos      = (const int*)  d_in[4];
    const float* cls_W    = (const float*)d_in[5];
    const float* cls_b    = (const float*)d_in[6];
    const float* env_W    = (const float*)d_in[7];
    const float* env_b    = (const float*)d_in[8];
    const float* clsclf_W = (const float*)d_in[9];
    const float* clsclf_b = (const float*)d_in[10];
    const float* envclf_W = (const float*)d_in[11];
    const float* envclf_b = (const float*)d_in[12];
    const float* cls_c1   = (const float*)d_in[13];
    const float* cls_c2   = (const float*)d_in[14];
    const float* env_c1   = (const float*)d_in[15];
    const float* env_c2   = (const float*)d_in[16];
    float* out = (float*)d_out;

    k_fused<<<MATVEC_BLOCKS + TOPK_BLOCKS + BIAS_BLOCKS, 512>>>(
        attn1, attn2, pos, cls_W, env_W, cls_b, env_b,
        clsclf_W, envclf_W, cls_c1, cls_c2, env_c1, env_c2);

    k_dots<<<DOT_BLOCKS, 256>>>(rep1, rep2, clsclf_b, envclf_b, out);
}